// round 1
// baseline (speedup 1.0000x reference)
#include <cuda_runtime.h>

#define BB      16
#define HH      32
#define DD      128
#define HIDDEN  4096      // HH*DD
#define MB      128
#define BSZ     16
#define SMAX    2048      // MB*BSZ
#define SPLITS  4
#define SPLIT_S (SMAX / SPLITS)   // 512
#define EPS     1e-6f
#define SCALE   0.08838834764831845f   // 1/sqrt(128)

// Persistent device scratch (no allocations allowed in kernel_launch)
__device__ float g_q [BB * HIDDEN];
__device__ float g_pm[BB * HH * SPLITS];
__device__ float g_pl[BB * HH * SPLITS];
__device__ float g_po[BB * HH * SPLITS * DD];

// ---------------------------------------------------------------------------
// Kernel 1: RMSNorm -> q.   grid = B, block = 256
// ---------------------------------------------------------------------------
__global__ void rms_kernel(const float* __restrict__ x, const float* __restrict__ w) {
    int b   = blockIdx.x;
    int tid = threadIdx.x;
    const float4* xp = (const float4*)(x + (size_t)b * HIDDEN);

    float4 v[4];
    float  s = 0.f;
#pragma unroll
    for (int i = 0; i < 4; i++) {
        v[i] = xp[tid + i * 256];
        s += v[i].x * v[i].x + v[i].y * v[i].y + v[i].z * v[i].z + v[i].w * v[i].w;
    }

    __shared__ float red[8];
#pragma unroll
    for (int o = 16; o; o >>= 1) s += __shfl_xor_sync(0xffffffffu, s, o);
    if ((tid & 31) == 0) red[tid >> 5] = s;
    __syncthreads();
    if (tid == 0) {
        float t = 0.f;
#pragma unroll
        for (int i = 0; i < 8; i++) t += red[i];
        red[0] = t;
    }
    __syncthreads();

    float inv = rsqrtf(red[0] * (1.0f / HIDDEN) + EPS);

    const float4* wp = (const float4*)w;
    float4*       qp = (float4*)(g_q + (size_t)b * HIDDEN);
#pragma unroll
    for (int i = 0; i < 4; i++) {
        float4 wv = wp[tid + i * 256];
        float4 o;
        o.x = v[i].x * inv * wv.x;
        o.y = v[i].y * inv * wv.y;
        o.z = v[i].z * inv * wv.z;
        o.w = v[i].w * inv * wv.w;
        qp[tid + i * 256] = o;
    }
}

// ---------------------------------------------------------------------------
// Kernel 2: flash-decoding partials.  grid = B*H*SPLITS, block = 256
// ---------------------------------------------------------------------------
__global__ void attn_partial(const float* __restrict__ kc,
                             const float* __restrict__ vc,
                             const int*   __restrict__ bt,
                             const int*   __restrict__ ctx) {
    int idx   = blockIdx.x;
    int split = idx & (SPLITS - 1);
    int bh    = idx >> 2;
    int h     = bh & (HH - 1);
    int b     = bh >> 5;
    int tid   = threadIdx.x;

    int n_ctx = ctx[b];
    int start = split * SPLIT_S;
    int end   = min(n_ctx, start + SPLIT_S);

    if (end <= start) {
        if (tid == 0) { g_pm[idx] = -1e30f; g_pl[idx] = 0.f; }
        return;
    }

    __shared__ float sc[SPLIT_S];
    __shared__ float red[8];
    __shared__ float accs[DD];

    int warp = tid >> 5;
    int lane = tid & 31;

    // q row for this (b,h): 128 floats -> one float4 per lane
    float4 qv = ((const float4*)(g_q + (size_t)b * HIDDEN + h * DD))[lane];

    // ---- phase A: scores[s] = scale * (q . K[s]) ; one warp per position ----
    for (int s = start + warp; s < end; s += 8) {
        int blk = __ldg(&bt[b * MB + (s >> 4)]);
        const float4* kp =
            (const float4*)(kc + ((((size_t)blk) * BSZ + (s & 15)) * HH + h) * DD);
        float4 kv = kp[lane];
        float  p  = qv.x * kv.x + qv.y * kv.y + qv.z * kv.z + qv.w * kv.w;
        p += __shfl_xor_sync(0xffffffffu, p, 16);
        p += __shfl_xor_sync(0xffffffffu, p, 8);
        p += __shfl_xor_sync(0xffffffffu, p, 4);
        p += __shfl_xor_sync(0xffffffffu, p, 2);
        p += __shfl_xor_sync(0xffffffffu, p, 1);
        if (lane == 0) sc[s - start] = p * SCALE;
    }
    __syncthreads();

    int n = end - start;

    // ---- phase B: block max, exp, block sum ----
    float m = -1e30f;
    for (int i = tid; i < n; i += 256) m = fmaxf(m, sc[i]);
#pragma unroll
    for (int o = 16; o; o >>= 1) m = fmaxf(m, __shfl_xor_sync(0xffffffffu, m, o));
    if (lane == 0) red[warp] = m;
    __syncthreads();
    m = red[0];
#pragma unroll
    for (int i = 1; i < 8; i++) m = fmaxf(m, red[i]);
    __syncthreads();   // everyone done reading red (max) before reuse for sum

    float l = 0.f;
    for (int i = tid; i < n; i += 256) {
        float e = __expf(sc[i] - m);
        sc[i]   = e;
        l += e;
    }
#pragma unroll
    for (int o = 16; o; o >>= 1) l += __shfl_xor_sync(0xffffffffu, l, o);
    if (lane == 0) red[warp] = l;
    __syncthreads();   // sc[] and red[] (sums) visible to all

    // ---- phase C: acc[d] = sum_s e_s * V[s][d] ; 128 channels x 2-way s ----
    int   d    = tid & (DD - 1);
    int   half = tid >> 7;
    float acc  = 0.f;
#pragma unroll 4
    for (int s = start + half; s < end; s += 2) {
        int blk = __ldg(&bt[b * MB + (s >> 4)]);
        float v = __ldg(&vc[((((size_t)blk) * BSZ + (s & 15)) * HH + h) * DD + d]);
        acc += sc[s - start] * v;
    }
    if (half == 0) accs[d] = acc;
    __syncthreads();
    if (half == 1) accs[d] += acc;
    __syncthreads();

    if (tid < DD) g_po[(size_t)idx * DD + tid] = accs[tid];
    if (tid == 0) {
        g_pm[idx] = m;
        float L = 0.f;
#pragma unroll
        for (int i = 0; i < 8; i++) L += red[i];
        g_pl[idx] = L;
    }
}

// ---------------------------------------------------------------------------
// Kernel 3: combine partials + residual.  grid = B*H, block = 128
// ---------------------------------------------------------------------------
__global__ void combine_kernel(const float* __restrict__ hidden,
                               float*       __restrict__ out) {
    int bh = blockIdx.x;
    int d  = threadIdx.x;

    float ms[SPLITS], ls[SPLITS];
    float M = -1e30f;
#pragma unroll
    for (int i = 0; i < SPLITS; i++) {
        ms[i] = g_pm[bh * SPLITS + i];
        ls[i] = g_pl[bh * SPLITS + i];
        M = fmaxf(M, ms[i]);
    }

    float L = 0.f, A = 0.f;
#pragma unroll
    for (int i = 0; i < SPLITS; i++) {
        if (ls[i] > 0.f) {
            float w = __expf(ms[i] - M);
            L += ls[i] * w;
            A += w * g_po[(size_t)(bh * SPLITS + i) * DD + d];
        }
    }

    int o = bh * DD + d;      // == b*HIDDEN + h*DD + d
    out[o] = hidden[o] + A / L;
}

// ---------------------------------------------------------------------------
extern "C" void kernel_launch(void* const* d_in, const int* in_sizes, int n_in,
                              void* d_out, int out_size) {
    const float* hidden = (const float*)d_in[0];
    const float* kc     = (const float*)d_in[1];
    const float* vc     = (const float*)d_in[2];
    const int*   bt     = (const int*)  d_in[3];
    const int*   ctx    = (const int*)  d_in[4];
    const float* w      = (const float*)d_in[5];
    float*       out    = (float*)d_out;

    rms_kernel   <<<BB,               256>>>(hidden, w);
    attn_partial <<<BB * HH * SPLITS, 256>>>(kc, vc, bt, ctx);
    combine_kernel<<<BB * HH,         DD >>>(hidden, out);
}

// round 2
// speedup vs baseline: 1.2973x; 1.2973x over previous
#include <cuda_runtime.h>

#define BB      16
#define HH      32
#define DD      128
#define HIDDEN  4096      // HH*DD
#define MB      128
#define BSZ     16
#define SMAX    2048      // MB*BSZ
#define SPLITS  8
#define SPLIT_S (SMAX / SPLITS)   // 256
#define EPS     1e-6f
#define SCALE   0.08838834764831845f   // 1/sqrt(128)

// Persistent device scratch (no allocations allowed in kernel_launch)
__device__ float g_q [BB * HIDDEN];
__device__ float g_pm[BB * HH * SPLITS];
__device__ float g_pl[BB * HH * SPLITS];
__device__ float g_po[BB * HH * SPLITS * DD];

// ---------------------------------------------------------------------------
// Kernel 1: RMSNorm -> q.   grid = B, block = 256
// ---------------------------------------------------------------------------
__global__ void rms_kernel(const float* __restrict__ x, const float* __restrict__ w) {
    int b   = blockIdx.x;
    int tid = threadIdx.x;
    const float4* xp = (const float4*)(x + (size_t)b * HIDDEN);

    float4 v[4];
    float  s = 0.f;
#pragma unroll
    for (int i = 0; i < 4; i++) {
        v[i] = xp[tid + i * 256];
        s += v[i].x * v[i].x + v[i].y * v[i].y + v[i].z * v[i].z + v[i].w * v[i].w;
    }

    __shared__ float red[8];
#pragma unroll
    for (int o = 16; o; o >>= 1) s += __shfl_xor_sync(0xffffffffu, s, o);
    if ((tid & 31) == 0) red[tid >> 5] = s;
    __syncthreads();
    if (tid == 0) {
        float t = 0.f;
#pragma unroll
        for (int i = 0; i < 8; i++) t += red[i];
        red[0] = t;
    }
    __syncthreads();

    float inv = rsqrtf(red[0] * (1.0f / HIDDEN) + EPS);

    const float4* wp = (const float4*)w;
    float4*       qp = (float4*)(g_q + (size_t)b * HIDDEN);
#pragma unroll
    for (int i = 0; i < 4; i++) {
        float4 wv = wp[tid + i * 256];
        float4 o;
        o.x = v[i].x * inv * wv.x;
        o.y = v[i].y * inv * wv.y;
        o.z = v[i].z * inv * wv.z;
        o.w = v[i].w * inv * wv.w;
        qp[tid + i * 256] = o;
    }
}

// ---------------------------------------------------------------------------
// Kernel 2: flash-decoding partials.  grid = B*H*SPLITS, block = 256
// Each warp handles 4 positions per iteration (independent loads -> MLP=4).
// ---------------------------------------------------------------------------
__global__ void attn_partial(const float* __restrict__ kc,
                             const float* __restrict__ vc,
                             const int*   __restrict__ bt,
                             const int*   __restrict__ ctx) {
    int idx   = blockIdx.x;
    int split = idx & (SPLITS - 1);
    int bh    = idx >> 3;
    int h     = bh & (HH - 1);
    int b     = bh >> 5;
    int tid   = threadIdx.x;

    int n_ctx = ctx[b];
    int start = split * SPLIT_S;
    int end   = min(n_ctx, start + SPLIT_S);

    if (end <= start) {
        if (tid == 0) { g_pm[idx] = -1e30f; g_pl[idx] = 0.f; }
        return;
    }

    __shared__ float sc[SPLIT_S];        // 1 KB
    __shared__ float red[8];
    __shared__ int   tbl[SPLIT_S / BSZ]; // 16 block-table entries for this split
    __shared__ float accs[8 * DD];       // 4 KB: per-warp V partials

    int warp = tid >> 5;
    int lane = tid & 31;

    if (tid < SPLIT_S / BSZ)
        tbl[tid] = bt[b * MB + (start >> 4) + tid];

    // q row for this (b,h): 128 floats -> one float4 per lane
    float4 qv = ((const float4*)(g_q + (size_t)b * HIDDEN + h * DD))[lane];
    __syncthreads();

    // ---- phase A: scores[s] = scale * (q . K[s]) ----
    // warp w covers positions [start+4w, start+4w+3], stride 32
    for (int s0 = start + warp * 4; s0 < end; s0 += 32) {
        int cnt = min(4, end - s0);
        float p[4];
#pragma unroll
        for (int j = 0; j < 4; j++) {
            p[j] = 0.f;
            if (j < cnt) {
                int s   = s0 + j;
                int blk = tbl[(s - start) >> 4];
                const float4* kp =
                    (const float4*)(kc + ((((size_t)blk) * BSZ + (s & 15)) * HH + h) * DD);
                float4 kv = kp[lane];
                p[j] = qv.x * kv.x + qv.y * kv.y + qv.z * kv.z + qv.w * kv.w;
            }
        }
#pragma unroll
        for (int j = 0; j < 4; j++) {
#pragma unroll
            for (int o = 16; o; o >>= 1)
                p[j] += __shfl_xor_sync(0xffffffffu, p[j], o);
        }
        if (lane == 0) {
#pragma unroll
            for (int j = 0; j < 4; j++)
                if (j < cnt) sc[s0 - start + j] = p[j] * SCALE;
        }
    }
    __syncthreads();

    int n = end - start;   // <= 256

    // ---- phase B: block max, exp, block sum (one element per thread) ----
    float m = (tid < n) ? sc[tid] : -1e30f;
#pragma unroll
    for (int o = 16; o; o >>= 1) m = fmaxf(m, __shfl_xor_sync(0xffffffffu, m, o));
    if (lane == 0) red[warp] = m;
    __syncthreads();
    m = red[0];
#pragma unroll
    for (int i = 1; i < 8; i++) m = fmaxf(m, red[i]);
    __syncthreads();

    float l = 0.f;
    if (tid < n) {
        float e = __expf(sc[tid] - m);
        sc[tid] = e;
        l = e;
    }
#pragma unroll
    for (int o = 16; o; o >>= 1) l += __shfl_xor_sync(0xffffffffu, l, o);
    if (lane == 0) red[warp] = l;
    __syncthreads();   // sc[] and red[] (sums) visible

    // ---- phase C: acc[d] += e_s * V[s][d] ----
    // warp owns same position groups as phase A; lane owns 4 channels (float4)
    float4 acc = make_float4(0.f, 0.f, 0.f, 0.f);
    for (int s0 = start + warp * 4; s0 < end; s0 += 32) {
        int cnt = min(4, end - s0);
#pragma unroll
        for (int j = 0; j < 4; j++) {
            if (j < cnt) {
                int s   = s0 + j;
                int blk = tbl[(s - start) >> 4];
                const float4* vp =
                    (const float4*)(vc + ((((size_t)blk) * BSZ + (s & 15)) * HH + h) * DD);
                float4 vv = vp[lane];
                float  e  = sc[s - start];
                acc.x += e * vv.x;
                acc.y += e * vv.y;
                acc.z += e * vv.z;
                acc.w += e * vv.w;
            }
        }
    }
    ((float4*)accs)[warp * 32 + lane] = acc;
    __syncthreads();

    // reduce 8 warp-partials per channel; threads 0..127 own channels
    if (tid < DD) {
        float a = 0.f;
#pragma unroll
        for (int g = 0; g < 8; g++) a += accs[g * DD + tid];
        g_po[(size_t)idx * DD + tid] = a;
    }
    if (tid == 0) {
        g_pm[idx] = m;
        float L = 0.f;
#pragma unroll
        for (int i = 0; i < 8; i++) L += red[i];
        g_pl[idx] = L;
    }
}

// ---------------------------------------------------------------------------
// Kernel 3: combine partials + residual.  grid = B*H, block = 128
// ---------------------------------------------------------------------------
__global__ void combine_kernel(const float* __restrict__ hidden,
                               float*       __restrict__ out) {
    int bh = blockIdx.x;
    int d  = threadIdx.x;

    float ms[SPLITS], ls[SPLITS];
    float M = -1e30f;
#pragma unroll
    for (int i = 0; i < SPLITS; i++) {
        ms[i] = g_pm[bh * SPLITS + i];
        ls[i] = g_pl[bh * SPLITS + i];
        M = fmaxf(M, ms[i]);
    }

    float L = 0.f, A = 0.f;
#pragma unroll
    for (int i = 0; i < SPLITS; i++) {
        if (ls[i] > 0.f) {
            float w = __expf(ms[i] - M);
            L += ls[i] * w;
            A += w * g_po[(size_t)(bh * SPLITS + i) * DD + d];
        }
    }

    int o = bh * DD + d;      // == b*HIDDEN + h*DD + d
    out[o] = hidden[o] + A / L;
}

// ---------------------------------------------------------------------------
extern "C" void kernel_launch(void* const* d_in, const int* in_sizes, int n_in,
                              void* d_out, int out_size) {
    const float* hidden = (const float*)d_in[0];
    const float* kc     = (const float*)d_in[1];
    const float* vc     = (const float*)d_in[2];
    const int*   bt     = (const int*)  d_in[3];
    const int*   ctx    = (const int*)  d_in[4];
    const float* w      = (const float*)d_in[5];
    float*       out    = (float*)d_out;

    rms_kernel    <<<BB,               256>>>(hidden, w);
    attn_partial  <<<BB * HH * SPLITS, 256>>>(kc, vc, bt, ctx);
    combine_kernel<<<BB * HH,          DD >>>(hidden, out);
}